// round 1
// baseline (speedup 1.0000x reference)
#include <cuda_runtime.h>
#include <cstdint>

// ---------------- problem constants (registry shapes) ----------------
#define NN      10000          // nodes per graph
#define EMAXE   320000         // edges (without self loops)
#define E2MAX   (EMAXE + NN)   // + self loops
#define BBMAX   4              // batch

// ---------------- device scratch (no allocations allowed) -------------
__device__ int   g_src[E2MAX];
__device__ int   g_dst[E2MAX];
__device__ int   g_esrc[E2MAX];        // CSR: src node per slot (sorted by dst)
__device__ int   g_indptr[NN + 1];
__device__ int   g_cursor[NN];
__device__ int   g_count[NN];
__device__ int   g_is64;
__device__ float g_h0 [BBMAX * NN * 256];   // layer0 pre-attention features
__device__ float g_hid[BBMAX * NN * 256];   // layer0 output / layer1 input
__device__ float g_h1 [BBMAX * NN * 128];   // layer1 pre-attention features
__device__ float g_als[BBMAX * NN];
__device__ float g_ald[BBMAX * NN];
__device__ float g_Wt0[256 * 256];
__device__ float g_Wt1[256 * 128];

// ---------------- edge preprocessing ----------------------------------

__global__ void zero_counts_kernel(int n) {
    int i = blockIdx.x * blockDim.x + threadIdx.x;
    if (i < n) g_count[i] = 0;
}

// Decide whether edge_index is int64 or int32: values < 2^31, so an int64
// little-endian layout has every odd 32-bit word == 0.
__global__ void detect_kernel(const unsigned int* __restrict__ w) {
    if (threadIdx.x == 0 && blockIdx.x == 0) {
        int ok = 1;
        for (int i = 1; i < 256; i += 2) {
            if (w[i] != 0u) { ok = 0; break; }
        }
        g_is64 = ok;
    }
}

__global__ void convert_kernel(const void* __restrict__ edges, int E, int Nn) {
    int i = blockIdx.x * blockDim.x + threadIdx.x;
    int E2 = E + Nn;
    if (i >= E2) return;
    int s, d;
    if (i < E) {
        if (g_is64) {
            const long long* p = (const long long*)edges;
            s = (int)p[i];
            d = (int)p[E + i];
        } else {
            const int* p = (const int*)edges;
            s = p[i];
            d = p[E + i];
        }
    } else {               // self loop
        s = d = i - E;
    }
    g_src[i] = s;
    g_dst[i] = d;
    atomicAdd(&g_count[d], 1);
}

// single-block scan over N counts -> indptr (+cursor copy)
__global__ void scan_kernel(int Nn) {
    __shared__ int sp[1024];
    int tid = threadIdx.x;
    int IT = (Nn + 1023) / 1024;
    int start = tid * IT;
    int sum = 0;
    for (int i = 0; i < IT; i++) {
        int idx = start + i;
        if (idx < Nn) sum += g_count[idx];
    }
    sp[tid] = sum;
    __syncthreads();
    for (int o = 1; o < 1024; o <<= 1) {
        int v = 0;
        if (tid >= o) v = sp[tid - o];
        __syncthreads();
        if (tid >= o) sp[tid] += v;
        __syncthreads();
    }
    int run = (tid > 0) ? sp[tid - 1] : 0;
    for (int i = 0; i < IT; i++) {
        int idx = start + i;
        if (idx < Nn) {
            g_indptr[idx] = run;
            g_cursor[idx] = run;
            run += g_count[idx];
        }
    }
    if (tid == 1023) g_indptr[Nn] = run;
}

__global__ void scatter_kernel(int E2) {
    int i = blockIdx.x * blockDim.x + threadIdx.x;
    if (i >= E2) return;
    int d = g_dst[i];
    int pos = atomicAdd(&g_cursor[d], 1);
    g_esrc[pos] = g_src[i];
}

// ---------------- weight transpose ------------------------------------
// W [R][C] -> Wt [C][R]
__global__ void transpose_kernel(const float* __restrict__ W, float* __restrict__ Wt,
                                 int R, int C) {
    __shared__ float t[32][33];
    int c = blockIdx.x * 32 + threadIdx.x;
    int r0 = blockIdx.y * 32;
    for (int i = threadIdx.y; i < 32; i += 8) {
        int r = r0 + i;
        if (r < R && c < C) t[i][threadIdx.x] = W[(size_t)r * C + c];
    }
    __syncthreads();
    int rr = r0 + threadIdx.x;
    int cc = blockIdx.x * 32;
    for (int i = threadIdx.y; i < 32; i += 8) {
        int ccc = cc + i;
        if (ccc < C && rr < R) Wt[(size_t)ccc * R + rr] = t[threadIdx.x][i];
    }
}

// ---------------- fp32 SGEMM: C[M][Nc] = A[M][K] * Bm[K][Nc] -----------
__global__ __launch_bounds__(256, 2)
void sgemm_kernel(const float* __restrict__ A, const float* __restrict__ Bm,
                  float* __restrict__ C, int M, int Nc, int K) {
    constexpr int BM = 128, BN = 128, BK = 8, TM = 8, TN = 8;
    __shared__ float As[2][BK][BM + 4];
    __shared__ float Bs[2][BK][BN];
    int tid  = threadIdx.x;
    int tx   = tid & 15;
    int ty   = tid >> 4;
    int bm   = blockIdx.y * BM;
    int bn   = blockIdx.x * BN;
    int arow = tid >> 1;
    int acol = (tid & 1) * 4;
    int brow = tid >> 5;
    int bcol = (tid & 31) * 4;

    float acc[TM][TN];
#pragma unroll
    for (int i = 0; i < TM; i++)
#pragma unroll
        for (int j = 0; j < TN; j++) acc[i][j] = 0.f;

    auto loadA = [&](int kt, int buf) {
        int gr = bm + arow;
        float4 v = make_float4(0.f, 0.f, 0.f, 0.f);
        if (gr < M) v = *(const float4*)(A + (size_t)gr * K + kt + acol);
        As[buf][acol + 0][arow] = v.x;
        As[buf][acol + 1][arow] = v.y;
        As[buf][acol + 2][arow] = v.z;
        As[buf][acol + 3][arow] = v.w;
    };
    auto loadB = [&](int kt, int buf) {
        float4 v = *(const float4*)(Bm + (size_t)(kt + brow) * Nc + bn + bcol);
        *(float4*)&Bs[buf][brow][bcol] = v;
    };

    loadA(0, 0);
    loadB(0, 0);
    __syncthreads();

    int nk = K / BK;
    for (int t = 0; t < nk; ++t) {
        int cur = t & 1, nxt = cur ^ 1;
        if (t + 1 < nk) {
            loadA((t + 1) * BK, nxt);
            loadB((t + 1) * BK, nxt);
        }
#pragma unroll
        for (int k = 0; k < BK; ++k) {
            float a[TM], b[TN];
#pragma unroll
            for (int i = 0; i < TM; i++) a[i] = As[cur][k][ty * TM + i];
#pragma unroll
            for (int j = 0; j < TN; j++) b[j] = Bs[cur][k][tx * TN + j];
#pragma unroll
            for (int i = 0; i < TM; i++)
#pragma unroll
                for (int j = 0; j < TN; j++) acc[i][j] += a[i] * b[j];
        }
        __syncthreads();
    }

#pragma unroll
    for (int i = 0; i < TM; i++) {
        int r = bm + ty * TM + i;
        if (r < M) {
#pragma unroll
            for (int j = 0; j < TN; j += 4) {
                float4 v = make_float4(acc[i][j], acc[i][j + 1], acc[i][j + 2], acc[i][j + 3]);
                *(float4*)(C + (size_t)r * Nc + bn + tx * TN + j) = v;
            }
        }
    }
}

// ---------------- attention-logit dot products -------------------------
template <int F>
__global__ void al_kernel(const float* __restrict__ h, const float* __restrict__ asrc,
                          const float* __restrict__ adst, float* __restrict__ als,
                          float* __restrict__ ald, int M) {
    int warp = (blockIdx.x * blockDim.x + threadIdx.x) >> 5;
    int lane = threadIdx.x & 31;
    if (warp >= M) return;
    const float* row = h + (size_t)warp * F;
    float s = 0.f, d = 0.f;
#pragma unroll
    for (int i = lane; i < F; i += 32) {
        float v = row[i];
        s += v * asrc[i];
        d += v * adst[i];
    }
#pragma unroll
    for (int o = 16; o; o >>= 1) {
        s += __shfl_xor_sync(0xffffffffu, s, o);
        d += __shfl_xor_sync(0xffffffffu, d, o);
    }
    if (!lane) {
        als[warp] = s;
        ald[warp] = d;
    }
}

// ---------------- softmax aggregation (one block per (batch,dst)) ------
template <int F>
__global__ __launch_bounds__(F)
void agg_kernel(const float* __restrict__ h, const float* __restrict__ als,
                const float* __restrict__ ald, const float* __restrict__ bias,
                float* __restrict__ out, int Nn) {
    constexpr int NW = F / 32;
    __shared__ float sred[NW];
    __shared__ float sbc;
    __shared__ float sw[F];
    __shared__ int   ssrc[F];

    int bx   = blockIdx.x;
    int v    = bx % Nn;
    int b    = bx / Nn;
    int tid  = threadIdx.x;
    int lane = tid & 31;
    int w    = tid >> 5;
    int begin = g_indptr[v];
    int end   = g_indptr[v + 1];
    int base  = b * Nn;
    float aldv = ald[base + v];

    // pass 1a: segment max
    float lm = -1e30f;
    for (int j = begin + tid; j < end; j += F) {
        float e = als[base + g_esrc[j]] + aldv;
        e = (e < 0.f) ? 0.2f * e : e;
        lm = fmaxf(lm, e);
    }
#pragma unroll
    for (int o = 16; o; o >>= 1) lm = fmaxf(lm, __shfl_xor_sync(0xffffffffu, lm, o));
    if (!lane) sred[w] = lm;
    __syncthreads();
    if (w == 0) {
        float x = (lane < NW) ? sred[lane] : -1e30f;
#pragma unroll
        for (int o = 16; o; o >>= 1) x = fmaxf(x, __shfl_xor_sync(0xffffffffu, x, o));
        if (!lane) sbc = x;
    }
    __syncthreads();
    float m = sbc;

    // pass 1b: denominator
    float ls = 0.f;
    for (int j = begin + tid; j < end; j += F) {
        float e = als[base + g_esrc[j]] + aldv;
        e = (e < 0.f) ? 0.2f * e : e;
        ls += __expf(e - m);
    }
#pragma unroll
    for (int o = 16; o; o >>= 1) ls += __shfl_xor_sync(0xffffffffu, ls, o);
    __syncthreads();
    if (!lane) sred[w] = ls;
    __syncthreads();
    if (w == 0) {
        float x = (lane < NW) ? sred[lane] : 0.f;
#pragma unroll
        for (int o = 16; o; o >>= 1) x += __shfl_xor_sync(0xffffffffu, x, o);
        if (!lane) sbc = x;
    }
    __syncthreads();
    float inv = 1.f / (sbc + 1e-16f);

    // pass 2: weighted feature aggregation, chunked through shared
    float acc = 0.f;
    for (int c0 = begin; c0 < end; c0 += F) {
        int len = min(F, end - c0);
        if (tid < len) {
            int s = g_esrc[c0 + tid];
            float e = als[base + s] + aldv;
            e = (e < 0.f) ? 0.2f * e : e;
            ssrc[tid] = s;
            sw[tid]   = __expf(e - m) * inv;
        }
        __syncthreads();
        int jj = 0;
        for (; jj + 4 <= len; jj += 4) {
            float w0 = sw[jj], w1 = sw[jj + 1], w2 = sw[jj + 2], w3 = sw[jj + 3];
            int   s0 = ssrc[jj], s1 = ssrc[jj + 1], s2 = ssrc[jj + 2], s3 = ssrc[jj + 3];
            float h0 = h[(size_t)(base + s0) * F + tid];
            float h1 = h[(size_t)(base + s1) * F + tid];
            float h2 = h[(size_t)(base + s2) * F + tid];
            float h3 = h[(size_t)(base + s3) * F + tid];
            acc += w0 * h0;
            acc += w1 * h1;
            acc += w2 * h2;
            acc += w3 * h3;
        }
        for (; jj < len; jj++)
            acc += sw[jj] * h[(size_t)(base + ssrc[jj]) * F + tid];
        __syncthreads();
    }

    float r = acc + bias[tid];
    out[(size_t)(base + v) * F + tid] = r > 0.f ? r : 0.f;
}

// ---------------- launch ----------------------------------------------
extern "C" void kernel_launch(void* const* d_in, const int* in_sizes, int n_in,
                              void* d_out, int out_size) {
    const float* x     = (const float*)d_in[0];
    const void*  edges = d_in[1];
    const float* W0    = (const float*)d_in[2];
    const float* b0    = (const float*)d_in[3];
    const float* asrc0 = (const float*)d_in[4];
    const float* adst0 = (const float*)d_in[5];
    const float* W1    = (const float*)d_in[6];
    const float* b1    = (const float*)d_in[7];
    const float* asrc1 = (const float*)d_in[8];
    const float* adst1 = (const float*)d_in[9];
    float* out = (float*)d_out;

    int F1 = in_sizes[3];            // 256
    int F0 = in_sizes[2] / F1;       // 256
    int F2 = in_sizes[7];            // 128
    int E  = in_sizes[1] / 2;        // 320000
    int M  = in_sizes[0] / F0;       // B*N = 40000
    int Nn = NN;                     // 10000
    int E2 = E + Nn;

    float *p_h0, *p_hid, *p_h1, *p_als, *p_ald, *p_wt0, *p_wt1;
    cudaGetSymbolAddress((void**)&p_h0,  g_h0);
    cudaGetSymbolAddress((void**)&p_hid, g_hid);
    cudaGetSymbolAddress((void**)&p_h1,  g_h1);
    cudaGetSymbolAddress((void**)&p_als, g_als);
    cudaGetSymbolAddress((void**)&p_ald, g_ald);
    cudaGetSymbolAddress((void**)&p_wt0, g_Wt0);
    cudaGetSymbolAddress((void**)&p_wt1, g_Wt1);

    // edge preprocessing (recomputed every launch; deterministic)
    zero_counts_kernel<<<(Nn + 255) / 256, 256>>>(Nn);
    detect_kernel<<<1, 32>>>((const unsigned int*)edges);
    convert_kernel<<<(E2 + 255) / 256, 256>>>(edges, E, Nn);
    scan_kernel<<<1, 1024>>>(Nn);
    scatter_kernel<<<(E2 + 255) / 256, 256>>>(E2);

    // weight transposes
    transpose_kernel<<<dim3((F0 + 31) / 32, (F1 + 31) / 32), dim3(32, 8)>>>(W0, p_wt0, F1, F0);
    transpose_kernel<<<dim3((F1 + 31) / 32, (F2 + 31) / 32), dim3(32, 8)>>>(W1, p_wt1, F2, F1);

    // ---- layer 0 ----
    sgemm_kernel<<<dim3(F1 / 128, (M + 127) / 128), 256>>>(x, p_wt0, p_h0, M, F1, F0);
    al_kernel<256><<<(M * 32 + 255) / 256, 256>>>(p_h0, asrc0, adst0, p_als, p_ald, M);
    agg_kernel<256><<<M, 256>>>(p_h0, p_als, p_ald, b0, p_hid, Nn);

    // ---- layer 1 ----
    sgemm_kernel<<<dim3(F2 / 128, (M + 127) / 128), 256>>>(p_hid, p_wt1, p_h1, M, F2, F1);
    al_kernel<128><<<(M * 32 + 255) / 256, 256>>>(p_h1, asrc1, adst1, p_als, p_ald, M);
    agg_kernel<128><<<M, 128>>>(p_h1, p_als, p_ald, b1, out, Nn);
}

// round 2
// speedup vs baseline: 1.2959x; 1.2959x over previous
#include <cuda_runtime.h>
#include <cuda_bf16.h>
#include <cstdint>

// ---------------- problem constants (registry shapes) ----------------
#define NN      10000          // nodes per graph
#define EMAXE   320000         // edges (without self loops)
#define E2MAX   (EMAXE + NN)   // + self loops
#define BBMAX   4              // batch

// ---------------- device scratch (no allocations allowed) -------------
__device__ int   g_src[E2MAX];
__device__ int   g_dst[E2MAX];
__device__ int   g_esrc[E2MAX];        // CSR: src node per slot (sorted by dst)
__device__ int   g_indptr[NN + 1];
__device__ int   g_cursor[NN];
__device__ int   g_count[NN];
__device__ int   g_is64;
__device__ float g_h0 [BBMAX * NN * 256];   // layer0 pre-attention features
__device__ float g_hid[BBMAX * NN * 256];   // layer0 output / layer1 input
__device__ float g_h1 [BBMAX * NN * 128];   // layer1 pre-attention features
__device__ float g_als[BBMAX * NN];
__device__ float g_ald[BBMAX * NN];

// ---------------- edge preprocessing ----------------------------------

__global__ void zero_counts_kernel(int n) {
    int i = blockIdx.x * blockDim.x + threadIdx.x;
    if (i < n) g_count[i] = 0;
}

// Decide whether edge_index is int64 or int32: values < 2^31, so an int64
// little-endian layout has every odd 32-bit word == 0.
__global__ void detect_kernel(const unsigned int* __restrict__ w) {
    if (threadIdx.x == 0 && blockIdx.x == 0) {
        int ok = 1;
        for (int i = 1; i < 256; i += 2) {
            if (w[i] != 0u) { ok = 0; break; }
        }
        g_is64 = ok;
    }
}

__global__ void convert_kernel(const void* __restrict__ edges, int E, int Nn) {
    int i = blockIdx.x * blockDim.x + threadIdx.x;
    int E2 = E + Nn;
    if (i >= E2) return;
    int s, d;
    if (i < E) {
        if (g_is64) {
            const long long* p = (const long long*)edges;
            s = (int)p[i];
            d = (int)p[E + i];
        } else {
            const int* p = (const int*)edges;
            s = p[i];
            d = p[E + i];
        }
    } else {               // self loop
        s = d = i - E;
    }
    g_src[i] = s;
    g_dst[i] = d;
    atomicAdd(&g_count[d], 1);
}

// single-block scan over N counts -> indptr (+cursor copy), warp-shuffle version
__global__ void scan_kernel(int Nn) {
    __shared__ int wsum[32];
    int tid  = threadIdx.x;            // 1024 threads
    int lane = tid & 31;
    int w    = tid >> 5;
    int IT   = (Nn + 1023) / 1024;     // 10 for Nn=10000
    int start = tid * IT;
    int loc[16];
    int sum = 0;
#pragma unroll
    for (int i = 0; i < 16; i++) {
        if (i < IT) {
            int idx = start + i;
            loc[i] = (idx < Nn) ? g_count[idx] : 0;
            sum += loc[i];
        }
    }
    // warp inclusive scan
    int s = sum;
#pragma unroll
    for (int o = 1; o < 32; o <<= 1) {
        int v = __shfl_up_sync(0xffffffffu, s, o);
        if (lane >= o) s += v;
    }
    if (lane == 31) wsum[w] = s;
    __syncthreads();
    if (w == 0) {
        int x = wsum[lane];
#pragma unroll
        for (int o = 1; o < 32; o <<= 1) {
            int v = __shfl_up_sync(0xffffffffu, x, o);
            if (lane >= o) x += v;
        }
        wsum[lane] = x;
    }
    __syncthreads();
    int base = s - sum + (w > 0 ? wsum[w - 1] : 0);   // exclusive prefix
    int run = base;
#pragma unroll
    for (int i = 0; i < 16; i++) {
        if (i < IT) {
            int idx = start + i;
            if (idx < Nn) {
                g_indptr[idx] = run;
                g_cursor[idx] = run;
                run += loc[i];
            }
        }
    }
    if (tid == 1023) g_indptr[Nn] = run;
}

__global__ void scatter_kernel(int E2) {
    int i = blockIdx.x * blockDim.x + threadIdx.x;
    if (i >= E2) return;
    int d = g_dst[i];
    int pos = atomicAdd(&g_cursor[d], 1);
    g_esrc[pos] = g_src[i];
}

// ---------------- bf16x3 split-precision tensor-core GEMM --------------
// C[M][N] = A[M][K] * W[N][K]^T   (mma row.col: B operand is W's native layout)
// fp32 operands split into hi/lo bf16; products hi*hi + hi*lo + lo*hi.

#define MMA8(c, a0, a1, b)                                                    \
    asm volatile(                                                             \
        "mma.sync.aligned.m16n8k8.row.col.f32.bf16.bf16.f32 "                 \
        "{%0,%1,%2,%3},{%4,%5},{%6},{%0,%1,%2,%3};"                           \
        : "+f"((c)[0]), "+f"((c)[1]), "+f"((c)[2]), "+f"((c)[3])              \
        : "r"(a0), "r"(a1), "r"(b))

__device__ __forceinline__ void split_store4(__nv_bfloat16* ph, __nv_bfloat16* pl,
                                             float4 v) {
    float f[4] = {v.x, v.y, v.z, v.w};
    __nv_bfloat16 h[4], l[4];
#pragma unroll
    for (int j = 0; j < 4; j++) {
        h[j] = __float2bfloat16(f[j]);
        l[j] = __float2bfloat16(f[j] - __bfloat162float(h[j]));
    }
    __nv_bfloat162 t;
    t.x = h[0]; t.y = h[1]; *(__nv_bfloat162*)(ph)     = t;
    t.x = h[2]; t.y = h[3]; *(__nv_bfloat162*)(ph + 2) = t;
    t.x = l[0]; t.y = l[1]; *(__nv_bfloat162*)(pl)     = t;
    t.x = l[2]; t.y = l[3]; *(__nv_bfloat162*)(pl + 2) = t;
}

__global__ __launch_bounds__(256, 2)
void gemm_bf16x3_kernel(const float* __restrict__ A, const float* __restrict__ Bw,
                        float* __restrict__ C, int M, int N, int K) {
    constexpr int BK = 16;
    constexpr int AP = 24;              // padded row (bf16 elems): conflict-free
    __shared__ __nv_bfloat16 Ah[2][128 * AP];
    __shared__ __nv_bfloat16 Al[2][128 * AP];
    __shared__ __nv_bfloat16 Bh[2][128 * AP];
    __shared__ __nv_bfloat16 Bl[2][128 * AP];

    int tid  = threadIdx.x;
    int wid  = tid >> 5;
    int lane = tid & 31;
    int wm0  = (wid >> 2) * 64;         // warp tile 64x32
    int wn0  = (wid & 3) * 32;
    int g    = lane >> 2;               // 0..7
    int tg   = lane & 3;                // 0..3
    int m0   = blockIdx.y * 128;
    int n0   = blockIdx.x * 128;

    float acc[4][4][4];
#pragma unroll
    for (int mt = 0; mt < 4; mt++)
#pragma unroll
        for (int nt = 0; nt < 4; nt++)
#pragma unroll
            for (int j = 0; j < 4; j++) acc[mt][nt][j] = 0.f;

    // loader mapping: 2 float4 per thread per operand tile (128 rows x 4 f4)
    int r0a = (tid)          >> 2, cg0 = (tid)          & 3;
    int r1a = (tid + 256)    >> 2, cg1 = (tid + 256)    & 3;

    auto ldA = [&](int kt, int row, int cg) -> float4 {
        int gr = m0 + row;
        if (gr < M) return *(const float4*)(A + (size_t)gr * K + kt + cg * 4);
        return make_float4(0.f, 0.f, 0.f, 0.f);
    };
    auto ldB = [&](int kt, int row, int cg) -> float4 {
        return *(const float4*)(Bw + (size_t)(n0 + row) * K + kt + cg * 4);
    };
    auto stage = [&](int buf, float4 va0, float4 va1, float4 vb0, float4 vb1) {
        split_store4(&Ah[buf][r0a * AP + cg0 * 4], &Al[buf][r0a * AP + cg0 * 4], va0);
        split_store4(&Ah[buf][r1a * AP + cg1 * 4], &Al[buf][r1a * AP + cg1 * 4], va1);
        split_store4(&Bh[buf][r0a * AP + cg0 * 4], &Bl[buf][r0a * AP + cg0 * 4], vb0);
        split_store4(&Bh[buf][r1a * AP + cg1 * 4], &Bl[buf][r1a * AP + cg1 * 4], vb1);
    };
    auto compute = [&](int buf) {
#pragma unroll
        for (int ks = 0; ks < BK; ks += 8) {
            unsigned ah[4][2], alr[4][2], bh[4], blr[4];
#pragma unroll
            for (int mt = 0; mt < 4; mt++) {
                int rb = (wm0 + mt * 16 + g) * AP + ks + 2 * tg;
                ah[mt][0]  = *(const unsigned*)&Ah[buf][rb];
                ah[mt][1]  = *(const unsigned*)&Ah[buf][rb + 8 * AP];
                alr[mt][0] = *(const unsigned*)&Al[buf][rb];
                alr[mt][1] = *(const unsigned*)&Al[buf][rb + 8 * AP];
            }
#pragma unroll
            for (int nt = 0; nt < 4; nt++) {
                int cb = (wn0 + nt * 8 + g) * AP + ks + 2 * tg;
                bh[nt]  = *(const unsigned*)&Bh[buf][cb];
                blr[nt] = *(const unsigned*)&Bl[buf][cb];
            }
#pragma unroll
            for (int mt = 0; mt < 4; mt++)
#pragma unroll
                for (int nt = 0; nt < 4; nt++) {
                    MMA8(acc[mt][nt], ah[mt][0],  ah[mt][1],  bh[nt]);
                    MMA8(acc[mt][nt], ah[mt][0],  ah[mt][1],  blr[nt]);
                    MMA8(acc[mt][nt], alr[mt][0], alr[mt][1], bh[nt]);
                }
        }
    };

    // prologue: stage tile 0
    {
        float4 va0 = ldA(0, r0a, cg0), va1 = ldA(0, r1a, cg1);
        float4 vb0 = ldB(0, r0a, cg0), vb1 = ldB(0, r1a, cg1);
        stage(0, va0, va1, vb0, vb1);
    }
    __syncthreads();

    int nk = K / BK;
    for (int t = 0; t < nk; ++t) {
        float4 va0, va1, vb0, vb1;
        bool more = (t + 1 < nk);
        if (more) {
            int kt = (t + 1) * BK;
            va0 = ldA(kt, r0a, cg0); va1 = ldA(kt, r1a, cg1);
            vb0 = ldB(kt, r0a, cg0); vb1 = ldB(kt, r1a, cg1);
        }
        compute(t & 1);
        if (more) stage((t + 1) & 1, va0, va1, vb0, vb1);
        __syncthreads();
    }

    // epilogue
#pragma unroll
    for (int mt = 0; mt < 4; mt++) {
        int r = m0 + wm0 + mt * 16 + g;
#pragma unroll
        for (int nt = 0; nt < 4; nt++) {
            int col = n0 + wn0 + nt * 8 + 2 * tg;
            if (r < M)
                *(float2*)(C + (size_t)r * N + col) =
                    make_float2(acc[mt][nt][0], acc[mt][nt][1]);
            if (r + 8 < M)
                *(float2*)(C + (size_t)(r + 8) * N + col) =
                    make_float2(acc[mt][nt][2], acc[mt][nt][3]);
        }
    }
}

// ---------------- attention-logit dot products -------------------------
template <int F>
__global__ void al_kernel(const float* __restrict__ h, const float* __restrict__ asrc,
                          const float* __restrict__ adst, float* __restrict__ als,
                          float* __restrict__ ald, int M) {
    int warp = (blockIdx.x * blockDim.x + threadIdx.x) >> 5;
    int lane = threadIdx.x & 31;
    if (warp >= M) return;
    const float* row = h + (size_t)warp * F;
    float s = 0.f, d = 0.f;
#pragma unroll
    for (int i = lane; i < F; i += 32) {
        float v = row[i];
        s += v * asrc[i];
        d += v * adst[i];
    }
#pragma unroll
    for (int o = 16; o; o >>= 1) {
        s += __shfl_xor_sync(0xffffffffu, s, o);
        d += __shfl_xor_sync(0xffffffffu, d, o);
    }
    if (!lane) {
        als[warp] = s;
        ald[warp] = d;
    }
}

// ---------------- softmax aggregation (one block per (batch,dst)) ------
template <int F>
__global__ __launch_bounds__(F)
void agg_kernel(const float* __restrict__ h, const float* __restrict__ als,
                const float* __restrict__ ald, const float* __restrict__ bias,
                float* __restrict__ out, int Nn) {
    constexpr int NW = F / 32;
    __shared__ float sred[NW];
    __shared__ float sbc;
    __shared__ float sw[F];
    __shared__ int   ssrc[F];

    int bx   = blockIdx.x;
    int v    = bx % Nn;
    int b    = bx / Nn;
    int tid  = threadIdx.x;
    int lane = tid & 31;
    int w    = tid >> 5;
    int begin = g_indptr[v];
    int end   = g_indptr[v + 1];
    int base  = b * Nn;
    float aldv = ald[base + v];

    // pass 1a: segment max
    float lm = -1e30f;
    for (int j = begin + tid; j < end; j += F) {
        float e = als[base + g_esrc[j]] + aldv;
        e = (e < 0.f) ? 0.2f * e : e;
        lm = fmaxf(lm, e);
    }
#pragma unroll
    for (int o = 16; o; o >>= 1) lm = fmaxf(lm, __shfl_xor_sync(0xffffffffu, lm, o));
    if (!lane) sred[w] = lm;
    __syncthreads();
    if (w == 0) {
        float x = (lane < NW) ? sred[lane] : -1e30f;
#pragma unroll
        for (int o = 16; o; o >>= 1) x = fmaxf(x, __shfl_xor_sync(0xffffffffu, x, o));
        if (!lane) sbc = x;
    }
    __syncthreads();
    float m = sbc;

    // pass 1b: denominator
    float ls = 0.f;
    for (int j = begin + tid; j < end; j += F) {
        float e = als[base + g_esrc[j]] + aldv;
        e = (e < 0.f) ? 0.2f * e : e;
        ls += __expf(e - m);
    }
#pragma unroll
    for (int o = 16; o; o >>= 1) ls += __shfl_xor_sync(0xffffffffu, ls, o);
    __syncthreads();
    if (!lane) sred[w] = ls;
    __syncthreads();
    if (w == 0) {
        float x = (lane < NW) ? sred[lane] : 0.f;
#pragma unroll
        for (int o = 16; o; o >>= 1) x += __shfl_xor_sync(0xffffffffu, x, o);
        if (!lane) sbc = x;
    }
    __syncthreads();
    float inv = 1.f / (sbc + 1e-16f);

    // pass 2: weighted feature aggregation, chunked through shared
    float acc = 0.f;
    for (int c0 = begin; c0 < end; c0 += F) {
        int len = min(F, end - c0);
        if (tid < len) {
            int s = g_esrc[c0 + tid];
            float e = als[base + s] + aldv;
            e = (e < 0.f) ? 0.2f * e : e;
            ssrc[tid] = s;
            sw[tid]   = __expf(e - m) * inv;
        }
        __syncthreads();
        int jj = 0;
        for (; jj + 4 <= len; jj += 4) {
            float w0 = sw[jj], w1 = sw[jj + 1], w2 = sw[jj + 2], w3 = sw[jj + 3];
            int   s0 = ssrc[jj], s1 = ssrc[jj + 1], s2 = ssrc[jj + 2], s3 = ssrc[jj + 3];
            float h0 = h[(size_t)(base + s0) * F + tid];
            float h1 = h[(size_t)(base + s1) * F + tid];
            float h2 = h[(size_t)(base + s2) * F + tid];
            float h3 = h[(size_t)(base + s3) * F + tid];
            acc += w0 * h0;
            acc += w1 * h1;
            acc += w2 * h2;
            acc += w3 * h3;
        }
        for (; jj < len; jj++)
            acc += sw[jj] * h[(size_t)(base + ssrc[jj]) * F + tid];
        __syncthreads();
    }

    float r = acc + bias[tid];
    out[(size_t)(base + v) * F + tid] = r > 0.f ? r : 0.f;
}

// ---------------- launch ----------------------------------------------
extern "C" void kernel_launch(void* const* d_in, const int* in_sizes, int n_in,
                              void* d_out, int out_size) {
    const float* x     = (const float*)d_in[0];
    const void*  edges = d_in[1];
    const float* W0    = (const float*)d_in[2];
    const float* b0    = (const float*)d_in[3];
    const float* asrc0 = (const float*)d_in[4];
    const float* adst0 = (const float*)d_in[5];
    const float* W1    = (const float*)d_in[6];
    const float* b1    = (const float*)d_in[7];
    const float* asrc1 = (const float*)d_in[8];
    const float* adst1 = (const float*)d_in[9];
    float* out = (float*)d_out;

    int F1 = in_sizes[3];            // 256
    int F0 = in_sizes[2] / F1;       // 256
    int F2 = in_sizes[7];            // 128
    int E  = in_sizes[1] / 2;        // 320000
    int M  = in_sizes[0] / F0;       // B*N = 40000
    int Nn = NN;                     // 10000
    int E2 = E + Nn;

    float *p_h0, *p_hid, *p_h1, *p_als, *p_ald;
    cudaGetSymbolAddress((void**)&p_h0,  g_h0);
    cudaGetSymbolAddress((void**)&p_hid, g_hid);
    cudaGetSymbolAddress((void**)&p_h1,  g_h1);
    cudaGetSymbolAddress((void**)&p_als, g_als);
    cudaGetSymbolAddress((void**)&p_ald, g_ald);

    // edge preprocessing (recomputed every launch; deterministic)
    zero_counts_kernel<<<(Nn + 255) / 256, 256>>>(Nn);
    detect_kernel<<<1, 32>>>((const unsigned int*)edges);
    convert_kernel<<<(E2 + 255) / 256, 256>>>(edges, E, Nn);
    scan_kernel<<<1, 1024>>>(Nn);
    scatter_kernel<<<(E2 + 255) / 256, 256>>>(E2);

    // ---- layer 0 ----  (B operand = W0 native [F1][F0] layout; no transpose)
    gemm_bf16x3_kernel<<<dim3(F1 / 128, (M + 127) / 128), 256>>>(x, W0, p_h0, M, F1, F0);
    al_kernel<256><<<(M * 32 + 255) / 256, 256>>>(p_h0, asrc0, adst0, p_als, p_ald, M);
    agg_kernel<256><<<M, 256>>>(p_h0, p_als, p_ald, b0, p_hid, Nn);

    // ---- layer 1 ----
    gemm_bf16x3_kernel<<<dim3(F2 / 128, (M + 127) / 128), 256>>>(p_hid, W1, p_h1, M, F2, F1);
    al_kernel<128><<<(M * 32 + 255) / 256, 256>>>(p_h1, asrc1, adst1, p_als, p_ald, M);
    agg_kernel<128><<<M, 128>>>(p_h1, p_als, p_ald, b1, out, Nn);
}